// round 6
// baseline (speedup 1.0000x reference)
#include <cuda_runtime.h>
#include <cuda_bf16.h>

#define BB     4
#define NN     8192
#define CC     256
#define POOLN  2048
#define NBR    4
#define TILE_PTS    1024                 // smem vertex tile (first 1024 pts of batch)
#define TILE_FLOATS (TILE_PTS * 3)       // 12 KB
#define QPB    8                         // queries (warps) per block

__device__ __forceinline__ float decode_radius(const int* radius_raw)
{
    const unsigned rv = (unsigned)__ldg(radius_raw);
    return (rv & 0x7F800000u) ? __int_as_float((int)rv) : (float)(int)rv;
}

// Cooperative full-N rescan for one hard query. Kept out-of-line so its
// register appetite (staging + prefix machinery) doesn't inflate the hot
// easy path's frame; under the launch_bounds cap it may spill — fine, it
// runs for ~2% of queries only.
__device__ __noinline__
void hard_rescan(const float* __restrict__ vb,
                 const float* __restrict__ feat,
                 float* __restrict__ outF,
                 int b, int hs, int hn, float r2,
                 int* s_wsum, int* s_idx, int* s_total)
{
    const int t  = threadIdx.x;            // owns points [t*32, t*32+32)
    const int tl = t & 31;
    const int tw = t >> 5;

    const float hqx = vb[hn * 3 + 0];
    const float hqy = vb[hn * 3 + 1];
    const float hqz = vb[hn * 3 + 2];
    const float hsq = hqx * hqx + hqy * hqy + hqz * hqz;

    // qualify mask over 32 contiguous points (24 coalesced float4 loads)
    unsigned mask = 0;
    const float4* __restrict__ base4 = (const float4*)(vb + (size_t)t * 96);
    #pragma unroll
    for (int g = 0; g < 4; g++) {
        float4 v[6];
        #pragma unroll
        for (int u = 0; u < 6; u++) v[u] = base4[g * 6 + u];
        const float* f = (const float*)v;
        #pragma unroll
        for (int j = 0; j < 8; j++) {
            const float px = f[3 * j + 0];
            const float py = f[3 * j + 1];
            const float pz = f[3 * j + 2];
            const float d = -2.0f * (px * hqx + py * hqy + pz * hqz) + hsq
                            + (px * px + py * py + pz * pz);
            mask |= ((unsigned)(!(d > r2))) << (g * 8 + j);
        }
    }

    // block-wide exclusive prefix over popcounts (thread order == index order)
    const int c = __popc(mask);
    int x = c;
    #pragma unroll
    for (int o = 1; o < 32; o <<= 1) {
        const int y = __shfl_up_sync(0xFFFFFFFFu, x, o);
        if (tl >= o) x += y;
    }
    if (tl == 31) s_wsum[tw] = x;
    __syncthreads();
    if (t == 0) {
        int acc = 0;
        #pragma unroll
        for (int w = 0; w < 8; w++) { const int v = s_wsum[w]; s_wsum[w] = acc; acc += v; }
        *s_total = acc;
    }
    __syncthreads();
    const int pre = s_wsum[tw] + x - c;

    if (mask && pre < NBR) {
        unsigned m = mask;
        int p = pre;
        while (m && p < NBR) {
            s_idx[p++] = t * 32 + (__ffs(m) - 1);
            m &= m - 1;
        }
    }
    __syncthreads();
    if (t == 0) {
        const int tot = *s_total < NBR ? *s_total : NBR;   // >= 1 (self qualifies)
        for (int k = tot; k < NBR; k++) s_idx[k] = s_idx[0];
    }
    __syncthreads();

    if (t < CC / 4) {
        const float* fb = feat + (size_t)b * NN * CC;
        const float4 a0 = ((const float4*)(fb + (size_t)s_idx[0] * CC))[t];
        const float4 a1 = ((const float4*)(fb + (size_t)s_idx[1] * CC))[t];
        const float4 a2 = ((const float4*)(fb + (size_t)s_idx[2] * CC))[t];
        const float4 a3 = ((const float4*)(fb + (size_t)s_idx[3] * CC))[t];
        float4 r;
        r.x = fmaxf(fmaxf(a0.x, a1.x), fmaxf(a2.x, a3.x));
        r.y = fmaxf(fmaxf(a0.y, a1.y), fmaxf(a2.y, a3.y));
        r.z = fmaxf(fmaxf(a0.z, a1.z), fmaxf(a2.z, a3.z));
        r.w = fmaxf(fmaxf(a0.w, a1.w), fmaxf(a2.w, a3.w));
        ((float4*)(outF + ((size_t)b * POOLN + hs) * CC))[t] = r;
    }
    __syncthreads();   // protect s_* reuse across repeated calls
}

// Single fused kernel, occupancy-capped to keep the easy path at >=4 blocks/SM.
__global__ __launch_bounds__(256, 4)
void pool_fused_kernel(const float* __restrict__ verts,
                       const float* __restrict__ feat,
                       const int*   __restrict__ radius_raw,
                       const int*   __restrict__ sample_idx,
                       float* __restrict__ outV,
                       float* __restrict__ outF)
{
    __shared__ float    s_tile[TILE_FLOATS];
    __shared__ unsigned s_hard;            // bitmask of warps needing full rescan
    __shared__ int      s_wsum[8];
    __shared__ int      s_idx[NBR];
    __shared__ int      s_total;

    const int wid  = threadIdx.x >> 5;
    const int lane = threadIdx.x & 31;
    const int qid  = blockIdx.x * QPB + wid;   // block never straddles batches
    const int b    = qid >> 11;                // / POOLN
    const int s    = qid & (POOLN - 1);

    if (threadIdx.x == 0) s_hard = 0;

    const float radius = decode_radius(radius_raw);
    const float r2 = radius * radius;

    // Cooperative tile load: 768 float4, coalesced.
    {
        const float4* __restrict__ src = (const float4*)(verts + (size_t)b * NN * 3);
        float4* dst = (float4*)s_tile;
        #pragma unroll
        for (int i = 0; i < TILE_FLOATS / 4 / 256; i++)
            dst[threadIdx.x + 256 * i] = src[threadIdx.x + 256 * i];
    }

    const int n = sample_idx[s];
    const float* vb = verts + (size_t)b * NN * 3;
    const float qx = vb[n * 3 + 0];
    const float qy = vb[n * 3 + 1];
    const float qz = vb[n * 3 + 2];
    const float sqn = qx * qx + qy * qy + qz * qz;

    if (lane < 3) {
        const float v = (lane == 0) ? qx : (lane == 1) ? qy : qz;
        outV[((size_t)b * POOLN + s) * 3 + lane] = v;
    }

    __syncthreads();

    // ---- easy scan over smem tile: first NBR ascending qualifiers ----
    int idx[NBR];
    int cnt = 0;
    #pragma unroll
    for (int k = 0; k < NBR; k++) idx[k] = n;

    for (int base = 0; base < TILE_PTS; base += 128) {
        unsigned bal[4];
        #pragma unroll
        for (int t = 0; t < 4; t++) {
            const int p = base + t * 32 + lane;
            const float px = s_tile[3 * p + 0];
            const float py = s_tile[3 * p + 1];
            const float pz = s_tile[3 * p + 2];
            const float d = -2.0f * (px * qx + py * qy + pz * qz) + sqn
                            + (px * px + py * py + pz * pz);
            bal[t] = __ballot_sync(0xFFFFFFFFu, !(d > r2));
        }
        #pragma unroll
        for (int t = 0; t < 4; t++) {
            unsigned m = bal[t];
            while (m && cnt < NBR) {
                idx[cnt++] = base + t * 32 + (__ffs(m) - 1);
                m &= m - 1;
            }
        }
        if (cnt >= NBR) break;   // uniform (ballot-derived)
    }

    if (cnt < NBR) {
        if (lane == 0) atomicOr(&s_hard, 1u << wid);
    } else {
        // gather 4 feature rows, max, store
        const float* fb = feat + (size_t)b * NN * CC;
        const float4* __restrict__ f0 = (const float4*)(fb + (size_t)idx[0] * CC);
        const float4* __restrict__ f1 = (const float4*)(fb + (size_t)idx[1] * CC);
        const float4* __restrict__ f2 = (const float4*)(fb + (size_t)idx[2] * CC);
        const float4* __restrict__ f3 = (const float4*)(fb + (size_t)idx[3] * CC);
        float4* __restrict__ fo = (float4*)(outF + ((size_t)b * POOLN + s) * CC);
        #pragma unroll
        for (int j = 0; j < CC / 128; j++) {
            const int c = lane + j * 32;
            float4 a = f0[c];
            const float4 v1 = f1[c], v2 = f2[c], v3 = f3[c];
            a.x = fmaxf(fmaxf(a.x, v1.x), fmaxf(v2.x, v3.x));
            a.y = fmaxf(fmaxf(a.y, v1.y), fmaxf(v2.y, v3.y));
            a.z = fmaxf(fmaxf(a.z, v1.z), fmaxf(v2.z, v3.z));
            a.w = fmaxf(fmaxf(a.w, v1.w), fmaxf(v2.w, v3.w));
            fo[c] = a;
        }
    }

    __syncthreads();
    unsigned hm = s_hard;                      // uniform across the block

    // ---- cooperative full-N rescan for each hard warp in this block ----
    while (hm) {
        const int hw = __ffs(hm) - 1;
        hm &= hm - 1;
        const int hqid = blockIdx.x * QPB + hw;
        const int hs   = hqid & (POOLN - 1);
        const int hn   = sample_idx[hs];
        hard_rescan(vb, feat, outF, b, hs, hn, r2, s_wsum, s_idx, &s_total);
    }
}

extern "C" void kernel_launch(void* const* d_in, const int* in_sizes, int n_in,
                              void* d_out, int out_size)
{
    const float* verts      = (const float*)d_in[0];
    const float* feat       = (const float*)d_in[1];
    const int*   radius_raw = (const int*)  d_in[2];
    const int*   sample_idx = (const int*)  d_in[3];

    float* outV = (float*)d_out;
    float* outF = (float*)d_out + (size_t)BB * POOLN * 3;

    pool_fused_kernel<<<BB * POOLN / QPB, 256>>>(verts, feat, radius_raw,
                                                 sample_idx, outV, outF);
}

// round 7
// speedup vs baseline: 1.1581x; 1.1581x over previous
#include <cuda_runtime.h>
#include <cuda_bf16.h>

#define BB     4
#define NN     8192
#define CC     256
#define POOLN  2048
#define NBR    4
#define TILE_PTS   1024                  // smem tile: first 1024 points of the batch
#define TILE_FLOATS (TILE_PTS * 3)       // 12 KB
#define QPB    8                         // queries (warps) per block
#define HARD_GRID 256

__device__ int g_hard_list[BB * POOLN];
__device__ int g_hard_count;             // zero-initialized; self-resetting
__device__ int g_hard_done;              // zero-initialized; self-resetting

__device__ __forceinline__ float decode_radius(const int* radius_raw)
{
    const unsigned rv = (unsigned)__ldg(radius_raw);
    return (rv & 0x7F800000u) ? __int_as_float((int)rv) : (float)(int)rv;
}

// ---------------- Easy pass: 8 queries per block, smem vertex tile ----------------
__global__ __launch_bounds__(256)
void pool_easy_kernel(const float* __restrict__ verts,
                      const float* __restrict__ feat,
                      const int*   __restrict__ radius_raw,
                      const int*   __restrict__ sample_idx,
                      float* __restrict__ outV,
                      float* __restrict__ outF)
{
    __shared__ float s_tile[TILE_FLOATS];   // raw (x,y,z)*1024 of this batch

    const int wid  = threadIdx.x >> 5;
    const int lane = threadIdx.x & 31;
    const int qid  = blockIdx.x * QPB + wid;         // 0 .. BB*POOLN-1
    const int b    = qid >> 11;                      // / POOLN (uniform per block)
    const int s    = qid & (POOLN - 1);

    // Cooperative tile load: 768 float4 slots, coalesced.
    {
        const float4* __restrict__ src =
            (const float4*)(verts + (size_t)b * NN * 3);
        float4* dst = (float4*)s_tile;
        #pragma unroll
        for (int i = 0; i < TILE_FLOATS / 4 / 256; i++)
            dst[threadIdx.x + 256 * i] = src[threadIdx.x + 256 * i];
    }

    const int n = sample_idx[s];
    const float* vb = verts + (size_t)b * NN * 3;
    const float qx = vb[n * 3 + 0];
    const float qy = vb[n * 3 + 1];
    const float qz = vb[n * 3 + 2];
    const float sqn = qx * qx + qy * qy + qz * qz;

    const float radius = decode_radius(radius_raw);
    const float r2 = radius * radius;

    // vertices_pool (always written here)
    if (lane < 3) {
        const float v = (lane == 0) ? qx : (lane == 1) ? qy : qz;
        outV[((size_t)b * POOLN + s) * 3 + lane] = v;
    }

    __syncthreads();

    // ---- scan smem tile, first NBR ascending qualifiers ----
    int idx[NBR];
    int cnt = 0;
    #pragma unroll
    for (int k = 0; k < NBR; k++) idx[k] = n;

    for (int base = 0; base < TILE_PTS; base += 128) {
        unsigned bal[4];
        #pragma unroll
        for (int t = 0; t < 4; t++) {
            const int p = base + t * 32 + lane;
            const float px = s_tile[3 * p + 0];
            const float py = s_tile[3 * p + 1];
            const float pz = s_tile[3 * p + 2];
            const float d = -2.0f * (px * qx + py * qy + pz * qz) + sqn
                            + (px * px + py * py + pz * pz);
            bal[t] = __ballot_sync(0xFFFFFFFFu, !(d > r2));
        }
        #pragma unroll
        for (int t = 0; t < 4; t++) {
            unsigned m = bal[t];
            while (m && cnt < NBR) {
                idx[cnt++] = base + t * 32 + (__ffs(m) - 1);
                m &= m - 1;
            }
        }
        if (cnt >= NBR) break;   // uniform (ballot-derived)
    }

    if (cnt < NBR) {             // rare: defer to hard pass
        if (lane == 0) {
            const int pos = atomicAdd(&g_hard_count, 1);
            g_hard_list[pos] = qid;
        }
        return;
    }

    // ---- gather 4 feature rows (float4), max, store ----
    const float* fb = feat + (size_t)b * NN * CC;
    const float4* __restrict__ f0 = (const float4*)(fb + (size_t)idx[0] * CC);
    const float4* __restrict__ f1 = (const float4*)(fb + (size_t)idx[1] * CC);
    const float4* __restrict__ f2 = (const float4*)(fb + (size_t)idx[2] * CC);
    const float4* __restrict__ f3 = (const float4*)(fb + (size_t)idx[3] * CC);
    float4* __restrict__ fo = (float4*)(outF + ((size_t)b * POOLN + s) * CC);

    #pragma unroll
    for (int j = 0; j < CC / 128; j++) {
        const int c = lane + j * 32;
        float4 a = f0[c];
        const float4 v1 = f1[c], v2 = f2[c], v3 = f3[c];
        a.x = fmaxf(fmaxf(a.x, v1.x), fmaxf(v2.x, v3.x));
        a.y = fmaxf(fmaxf(a.y, v1.y), fmaxf(v2.y, v3.y));
        a.z = fmaxf(fmaxf(a.z, v1.z), fmaxf(v2.z, v3.z));
        a.w = fmaxf(fmaxf(a.w, v1.w), fmaxf(v2.w, v3.w));
        fo[c] = a;
    }
}

// ---------------- Hard pass: flagged queries spread over a fixed grid ----------------
// Self-cleans g_hard_count/g_hard_done at the end (last block) so the next
// graph replay starts from zero without a separate reset kernel.
__global__ __launch_bounds__(256)
void pool_hard_kernel(const float* __restrict__ verts,
                      const float* __restrict__ feat,
                      const int*   __restrict__ radius_raw,
                      const int*   __restrict__ sample_idx,
                      float* __restrict__ outF)
{
    const int nhard = g_hard_count;

    for (int it = blockIdx.x; it < nhard; it += gridDim.x) {
        const int qid = g_hard_list[it];
        const int b = qid >> 11;
        const int s = qid & (POOLN - 1);
        const int t = threadIdx.x;           // owns points [t*32, t*32+32)
        const int lane = t & 31;
        const int wid  = t >> 5;

        __shared__ int s_wsum[8];
        __shared__ int s_idx[NBR];
        __shared__ int s_total;

        const int n = sample_idx[s];
        const float radius = decode_radius(radius_raw);
        const float r2 = radius * radius;

        const float* vb = verts + (size_t)b * NN * 3;
        const float qx = vb[n * 3 + 0];
        const float qy = vb[n * 3 + 1];
        const float qz = vb[n * 3 + 2];
        const float sqn = qx * qx + qy * qy + qz * qz;

        // qualify mask over this thread's 32 contiguous points (float4 loads, MLP)
        unsigned mask = 0;
        const float4* __restrict__ base4 = (const float4*)(vb + (size_t)t * 96);
        #pragma unroll
        for (int g = 0; g < 4; g++) {        // 8 points per group = 6 float4
            float4 v[6];
            #pragma unroll
            for (int u = 0; u < 6; u++) v[u] = base4[g * 6 + u];
            const float* f = (const float*)v;
            #pragma unroll
            for (int j = 0; j < 8; j++) {
                const float px = f[3 * j + 0];
                const float py = f[3 * j + 1];
                const float pz = f[3 * j + 2];
                const float d = -2.0f * (px * qx + py * qy + pz * qz) + sqn
                                + (px * px + py * py + pz * pz);
                mask |= ((unsigned)(!(d > r2))) << (g * 8 + j);
            }
        }

        // block-wide exclusive prefix over popcounts (thread order == index order)
        const int c = __popc(mask);
        int x = c;
        #pragma unroll
        for (int o = 1; o < 32; o <<= 1) {
            const int y = __shfl_up_sync(0xFFFFFFFFu, x, o);
            if (lane >= o) x += y;
        }
        if (lane == 31) s_wsum[wid] = x;
        __syncthreads();
        if (t == 0) {
            int acc = 0;
            #pragma unroll
            for (int w = 0; w < 8; w++) { const int v = s_wsum[w]; s_wsum[w] = acc; acc += v; }
            s_total = acc;
        }
        __syncthreads();
        const int pre = s_wsum[wid] + x - c;

        if (mask && pre < NBR) {
            unsigned m = mask;
            int p = pre;
            while (m && p < NBR) {
                s_idx[p++] = t * 32 + (__ffs(m) - 1);
                m &= m - 1;
            }
        }
        __syncthreads();
        if (t == 0) {
            const int tot = s_total < NBR ? s_total : NBR;   // >= 1 (self qualifies)
            for (int k = tot; k < NBR; k++) s_idx[k] = s_idx[0];
        }
        __syncthreads();

        if (t < CC / 4) {
            const float* fb = feat + (size_t)b * NN * CC;
            const float4 a0 = ((const float4*)(fb + (size_t)s_idx[0] * CC))[t];
            const float4 a1 = ((const float4*)(fb + (size_t)s_idx[1] * CC))[t];
            const float4 a2 = ((const float4*)(fb + (size_t)s_idx[2] * CC))[t];
            const float4 a3 = ((const float4*)(fb + (size_t)s_idx[3] * CC))[t];
            float4 r;
            r.x = fmaxf(fmaxf(a0.x, a1.x), fmaxf(a2.x, a3.x));
            r.y = fmaxf(fmaxf(a0.y, a1.y), fmaxf(a2.y, a3.y));
            r.z = fmaxf(fmaxf(a0.z, a1.z), fmaxf(a2.z, a3.z));
            r.w = fmaxf(fmaxf(a0.w, a1.w), fmaxf(a2.w, a3.w));
            ((float4*)(outF + ((size_t)b * POOLN + s) * CC))[t] = r;
        }
        __syncthreads();   // protect s_* reuse across loop iterations
    }

    // ---- self-reset for next replay: last block zeroes the counters ----
    __syncthreads();
    if (threadIdx.x == 0) {
        __threadfence();
        const int done = atomicAdd(&g_hard_done, 1);
        if (done == (int)gridDim.x - 1) {
            g_hard_count = 0;
            g_hard_done  = 0;
            __threadfence();
        }
    }
}

extern "C" void kernel_launch(void* const* d_in, const int* in_sizes, int n_in,
                              void* d_out, int out_size)
{
    const float* verts      = (const float*)d_in[0];
    const float* feat       = (const float*)d_in[1];
    const int*   radius_raw = (const int*)  d_in[2];
    const int*   sample_idx = (const int*)  d_in[3];

    float* outV = (float*)d_out;
    float* outF = (float*)d_out + (size_t)BB * POOLN * 3;

    pool_easy_kernel<<<BB * POOLN / QPB, 256>>>(verts, feat, radius_raw,
                                                sample_idx, outV, outF);
    pool_hard_kernel<<<HARD_GRID, 256>>>(verts, feat, radius_raw, sample_idx, outF);
}

// round 8
// speedup vs baseline: 1.3012x; 1.1235x over previous
#include <cuda_runtime.h>
#include <cuda_bf16.h>

#define BB     4
#define NN     8192
#define CC     256
#define POOLN  2048
#define NBR    4
#define TILE_PTS   2048                  // smem tile: first 2048 points of the batch
#define TILE_FLOATS (TILE_PTS * 3)       // 24 KB
#define QPB    8                         // queries (warps) per block
#define HARD_GRID 1024

__device__ int g_hard_list[BB * POOLN];
__device__ int g_hard_count;             // zero-initialized; self-resetting
__device__ int g_hard_done;              // zero-initialized; self-resetting

__device__ __forceinline__ float decode_radius(const int* radius_raw)
{
    const unsigned rv = (unsigned)__ldg(radius_raw);
    return (rv & 0x7F800000u) ? __int_as_float((int)rv) : (float)(int)rv;
}

// ---------------- Easy pass: 8 queries per block, smem vertex tile ----------------
__global__ __launch_bounds__(256)
void pool_easy_kernel(const float* __restrict__ verts,
                      const float* __restrict__ feat,
                      const int*   __restrict__ radius_raw,
                      const int*   __restrict__ sample_idx,
                      float* __restrict__ outV,
                      float* __restrict__ outF)
{
    __shared__ float s_tile[TILE_FLOATS];   // raw (x,y,z)*2048 of this batch

    const int wid  = threadIdx.x >> 5;
    const int lane = threadIdx.x & 31;
    const int qid  = blockIdx.x * QPB + wid;         // 0 .. BB*POOLN-1
    const int b    = qid >> 11;                      // / POOLN (uniform per block)
    const int s    = qid & (POOLN - 1);

    // Cooperative tile load: 1536 float4 slots, coalesced.
    {
        const float4* __restrict__ src =
            (const float4*)(verts + (size_t)b * NN * 3);
        float4* dst = (float4*)s_tile;
        #pragma unroll
        for (int i = 0; i < TILE_FLOATS / 4 / 256; i++)
            dst[threadIdx.x + 256 * i] = src[threadIdx.x + 256 * i];
    }

    const int n = sample_idx[s];
    const float* vb = verts + (size_t)b * NN * 3;
    const float qx = vb[n * 3 + 0];
    const float qy = vb[n * 3 + 1];
    const float qz = vb[n * 3 + 2];
    const float sqn = qx * qx + qy * qy + qz * qz;

    const float radius = decode_radius(radius_raw);
    const float r2 = radius * radius;

    // vertices_pool (always written here)
    if (lane < 3) {
        const float v = (lane == 0) ? qx : (lane == 1) ? qy : qz;
        outV[((size_t)b * POOLN + s) * 3 + lane] = v;
    }

    __syncthreads();

    // ---- scan smem tile, first NBR ascending qualifiers ----
    int idx[NBR];
    int cnt = 0;
    #pragma unroll
    for (int k = 0; k < NBR; k++) idx[k] = n;

    for (int base = 0; base < TILE_PTS; base += 128) {
        unsigned bal[4];
        #pragma unroll
        for (int t = 0; t < 4; t++) {
            const int p = base + t * 32 + lane;
            const float px = s_tile[3 * p + 0];
            const float py = s_tile[3 * p + 1];
            const float pz = s_tile[3 * p + 2];
            const float d = -2.0f * (px * qx + py * qy + pz * qz) + sqn
                            + (px * px + py * py + pz * pz);
            bal[t] = __ballot_sync(0xFFFFFFFFu, !(d > r2));
        }
        #pragma unroll
        for (int t = 0; t < 4; t++) {
            unsigned m = bal[t];
            while (m && cnt < NBR) {
                idx[cnt++] = base + t * 32 + (__ffs(m) - 1);
                m &= m - 1;
            }
        }
        if (cnt >= NBR) break;   // uniform (ballot-derived)
    }

    if (cnt < NBR) {             // rare: defer to hard pass
        if (lane == 0) {
            const int pos = atomicAdd(&g_hard_count, 1);
            g_hard_list[pos] = qid;
        }
        return;
    }

    // ---- gather 4 feature rows (float4), max, store ----
    const float* fb = feat + (size_t)b * NN * CC;
    const float4* __restrict__ f0 = (const float4*)(fb + (size_t)idx[0] * CC);
    const float4* __restrict__ f1 = (const float4*)(fb + (size_t)idx[1] * CC);
    const float4* __restrict__ f2 = (const float4*)(fb + (size_t)idx[2] * CC);
    const float4* __restrict__ f3 = (const float4*)(fb + (size_t)idx[3] * CC);
    float4* __restrict__ fo = (float4*)(outF + ((size_t)b * POOLN + s) * CC);

    #pragma unroll
    for (int j = 0; j < CC / 128; j++) {
        const int c = lane + j * 32;
        float4 a = f0[c];
        const float4 v1 = f1[c], v2 = f2[c], v3 = f3[c];
        a.x = fmaxf(fmaxf(a.x, v1.x), fmaxf(v2.x, v3.x));
        a.y = fmaxf(fmaxf(a.y, v1.y), fmaxf(v2.y, v3.y));
        a.z = fmaxf(fmaxf(a.z, v1.z), fmaxf(v2.z, v3.z));
        a.w = fmaxf(fmaxf(a.w, v1.w), fmaxf(v2.w, v3.w));
        fo[c] = a;
    }
}

// ---------------- Hard pass: flagged queries, one block per query ----------------
// High register budget (minBlocks=2 -> up to 128 regs) so the 24 staged float4
// vertex loads per thread stay in flight instead of serializing at 32 regs.
__global__ __launch_bounds__(256, 2)
void pool_hard_kernel(const float* __restrict__ verts,
                      const float* __restrict__ feat,
                      const int*   __restrict__ radius_raw,
                      const int*   __restrict__ sample_idx,
                      float* __restrict__ outF)
{
    const int nhard = g_hard_count;
    const float radius = decode_radius(radius_raw);
    const float r2 = radius * radius;

    for (int it = blockIdx.x; it < nhard; it += gridDim.x) {
        const int qid = g_hard_list[it];
        const int b = qid >> 11;
        const int s = qid & (POOLN - 1);
        const int t = threadIdx.x;           // owns points [t*32, t*32+32)
        const int lane = t & 31;
        const int wid  = t >> 5;

        __shared__ int s_wsum[8];
        __shared__ int s_idx[NBR];
        __shared__ int s_total;

        const int n = sample_idx[s];
        const float* vb = verts + (size_t)b * NN * 3;
        const float qx = vb[n * 3 + 0];
        const float qy = vb[n * 3 + 1];
        const float qz = vb[n * 3 + 2];
        const float sqn = qx * qx + qy * qy + qz * qz;

        // qualify mask over this thread's 32 contiguous points.
        // Two batches of 12 float4 (16 points each), all loads of a batch in flight.
        unsigned mask = 0;
        const float4* __restrict__ base4 = (const float4*)(vb + (size_t)t * 96);
        #pragma unroll
        for (int h = 0; h < 2; h++) {
            float4 v[12];
            #pragma unroll
            for (int u = 0; u < 12; u++) v[u] = base4[h * 12 + u];
            const float* f = (const float*)v;
            #pragma unroll
            for (int j = 0; j < 16; j++) {
                const float px = f[3 * j + 0];
                const float py = f[3 * j + 1];
                const float pz = f[3 * j + 2];
                const float d = -2.0f * (px * qx + py * qy + pz * qz) + sqn
                                + (px * px + py * py + pz * pz);
                mask |= ((unsigned)(!(d > r2))) << (h * 16 + j);
            }
        }

        // block-wide exclusive prefix over popcounts (thread order == index order)
        const int c = __popc(mask);
        int x = c;
        #pragma unroll
        for (int o = 1; o < 32; o <<= 1) {
            const int y = __shfl_up_sync(0xFFFFFFFFu, x, o);
            if (lane >= o) x += y;
        }
        if (lane == 31) s_wsum[wid] = x;
        __syncthreads();
        if (t == 0) {
            int acc = 0;
            #pragma unroll
            for (int w = 0; w < 8; w++) { const int v = s_wsum[w]; s_wsum[w] = acc; acc += v; }
            s_total = acc;
        }
        __syncthreads();
        const int pre = s_wsum[wid] + x - c;

        if (mask && pre < NBR) {
            unsigned m = mask;
            int p = pre;
            while (m && p < NBR) {
                s_idx[p++] = t * 32 + (__ffs(m) - 1);
                m &= m - 1;
            }
        }
        __syncthreads();
        if (t == 0) {
            const int tot = s_total < NBR ? s_total : NBR;   // >= 1 (self qualifies)
            for (int k = tot; k < NBR; k++) s_idx[k] = s_idx[0];
        }
        __syncthreads();

        if (t < CC / 4) {
            const float* fb = feat + (size_t)b * NN * CC;
            const float4 a0 = ((const float4*)(fb + (size_t)s_idx[0] * CC))[t];
            const float4 a1 = ((const float4*)(fb + (size_t)s_idx[1] * CC))[t];
            const float4 a2 = ((const float4*)(fb + (size_t)s_idx[2] * CC))[t];
            const float4 a3 = ((const float4*)(fb + (size_t)s_idx[3] * CC))[t];
            float4 r;
            r.x = fmaxf(fmaxf(a0.x, a1.x), fmaxf(a2.x, a3.x));
            r.y = fmaxf(fmaxf(a0.y, a1.y), fmaxf(a2.y, a3.y));
            r.z = fmaxf(fmaxf(a0.z, a1.z), fmaxf(a2.z, a3.z));
            r.w = fmaxf(fmaxf(a0.w, a1.w), fmaxf(a2.w, a3.w));
            ((float4*)(outF + ((size_t)b * POOLN + s) * CC))[t] = r;
        }
        __syncthreads();   // protect s_* reuse across loop iterations
    }

    // ---- self-reset for next replay: last block zeroes the counters ----
    __syncthreads();
    if (threadIdx.x == 0) {
        __threadfence();
        const int done = atomicAdd(&g_hard_done, 1);
        if (done == (int)gridDim.x - 1) {
            g_hard_count = 0;
            g_hard_done  = 0;
            __threadfence();
        }
    }
}

extern "C" void kernel_launch(void* const* d_in, const int* in_sizes, int n_in,
                              void* d_out, int out_size)
{
    const float* verts      = (const float*)d_in[0];
    const float* feat       = (const float*)d_in[1];
    const int*   radius_raw = (const int*)  d_in[2];
    const int*   sample_idx = (const int*)  d_in[3];

    float* outV = (float*)d_out;
    float* outF = (float*)d_out + (size_t)BB * POOLN * 3;

    pool_easy_kernel<<<BB * POOLN / QPB, 256>>>(verts, feat, radius_raw,
                                                sample_idx, outV, outF);
    pool_hard_kernel<<<HARD_GRID, 256>>>(verts, feat, radius_raw, sample_idx, outF);
}